// round 12
// baseline (speedup 1.0000x reference)
#include <cuda_runtime.h>
#include <cuda_bf16.h>
#include <math.h>
#include <stdint.h>

// Problem constants
#define BB 2
#define SS 2048
#define EE 1024
#define HH 16
#define DD 64
#define BHH (BB*HH)          // 32
#define MTOK (BB*SS)         // 4096
#define ATT_SCALE 0.125f     // 64^-0.5

typedef unsigned long long ull;

// Scratch (device globals — no allocs allowed)
// Q: per-bh A-fragment-major (128-row blocks of 8192 floats), pre-scaled, tf32
// K: per-bh B-fragment-major (64-key chunks of 4096 floats, tiles (d8*8+key8)*64)
// V: per-bh B-fragment-major (64-key chunks of 4096 floats, tiles (key8*8+d8)*64)
__device__ float g_q[(long long)BHH*SS*DD];
__device__ float g_k[(long long)BHH*SS*DD];
__device__ float g_v[(long long)BHH*SS*DD];
__device__ float g_ctx[(long long)MTOK*EE];   // attn out, row-major
__device__ float g_xr[(long long)MTOK*EE];    // permA(x); later permA(ctx)
__device__ float g_wq[(long long)EE*EE];      // permB(weights)
__device__ float g_wk[(long long)EE*EE];
__device__ float g_wv[(long long)EE*EE];
__device__ float g_wo[(long long)EE*EE];

// ---------------------------------------------------------------------------
// PTX helpers
// ---------------------------------------------------------------------------
__device__ __forceinline__ float rna_tf32(float x) {
    uint32_t r;
    asm("cvt.rna.tf32.f32 %0, %1;" : "=r"(r) : "f"(x));
    return __uint_as_float(r);
}
__device__ __forceinline__ uint32_t smem_u32(const void* p) {
    return (uint32_t)__cvta_generic_to_shared(p);
}
__device__ __forceinline__ void mbar_init(uint32_t a, uint32_t cnt) {
    asm volatile("mbarrier.init.shared.b64 [%0], %1;" :: "r"(a), "r"(cnt) : "memory");
}
__device__ __forceinline__ void mbar_inval(uint32_t a) {
    asm volatile("mbarrier.inval.shared.b64 [%0];" :: "r"(a) : "memory");
}
__device__ __forceinline__ void mbar_expect(uint32_t a, uint32_t bytes) {
    asm volatile("mbarrier.arrive.expect_tx.shared.b64 _, [%0], %1;"
                 :: "r"(a), "r"(bytes) : "memory");
}
__device__ __forceinline__ void mbar_wait(uint32_t a, uint32_t parity) {
    asm volatile(
        "{\n\t.reg .pred P;\n\t"
        "WL%=:\n\t"
        "mbarrier.try_wait.parity.acquire.cta.shared::cta.b64 P, [%0], %1, 0x989680;\n\t"
        "@!P bra WL%=;\n\t}"
        :: "r"(a), "r"(parity) : "memory");
}
__device__ __forceinline__ void bulk_g2s(uint32_t dst, const void* src,
                                         uint32_t bytes, uint32_t mbar) {
    asm volatile(
        "cp.async.bulk.shared::cluster.global.mbarrier::complete_tx::bytes "
        "[%0], [%1], %2, [%3];"
        :: "r"(dst), "l"(src), "r"(bytes), "r"(mbar) : "memory");
}
__device__ __forceinline__ void cp16(void* dst, const void* src) {
    unsigned d = (unsigned)__cvta_generic_to_shared(dst);
    asm volatile("cp.async.cg.shared.global [%0], [%1], 16;\n" :: "r"(d), "l"(src));
}
__device__ __forceinline__ void cp_commit() { asm volatile("cp.async.commit_group;\n"); }
template<int N> __device__ __forceinline__ void cp_wait() {
    asm volatile("cp.async.wait_group %0;\n" :: "n"(N) : "memory");
}
// warp-level tf32 MMA: D(16x8) += A(16x8) @ B(8x8), fp32 accum
__device__ __forceinline__ void mma_tf32(float* c, const uint4& a, const uint2& b) {
    asm volatile(
        "mma.sync.aligned.m16n8k8.row.col.f32.tf32.tf32.f32 "
        "{%0,%1,%2,%3}, {%4,%5,%6,%7}, {%8,%9}, {%0,%1,%2,%3};"
        : "+f"(c[0]), "+f"(c[1]), "+f"(c[2]), "+f"(c[3])
        : "r"(a.x), "r"(a.y), "r"(a.z), "r"(a.w), "r"(b.x), "r"(b.y));
}

// ---------------------------------------------------------------------------
// Layout permutation kernels (fused tf32 rounding) — unchanged from R10.
// ---------------------------------------------------------------------------
__global__ __launch_bounds__(128) void permA_kernel(const float* __restrict__ src,
                                                    float* __restrict__ dst)
{
    __shared__ float s[32 * 132];
    const int kc = blockIdx.x, mb = blockIdx.y;
    const int tid = threadIdx.x;
    const float* sp = src + (long long)mb * 128 * EE + kc * 32;
#pragma unroll
    for (int it = 0; it < 8; it++) {
        int idx = tid + it * 128;
        int r = idx >> 3, cq = idx & 7;
        float4 v = *(const float4*)(sp + (long long)r * EE + cq * 4);
        float a4[4] = {rna_tf32(v.x), rna_tf32(v.y), rna_tf32(v.z), rna_tf32(v.w)};
        int mt = r >> 4, rm = r & 15;
#pragma unroll
        for (int u = 0; u < 4; u++) {
            int kcc = cq * 4 + u;
            int kt = kcc >> 3, kk = kcc & 7;
            int la = ((rm & 7) << 2) | (kk & 3);
            int ja = ((kk & 4) ? 2 : 0) | (rm >> 3);
            s[(mt * 4 + kt) * 132 + la * 4 + ja] = a4[u];
        }
    }
    __syncthreads();
    float* dp = dst + ((long long)mb * 32 + kc) * 4096;
#pragma unroll
    for (int j = 0; j < 8; j++) {
        int lin4 = tid + j * 128;
        int tile = lin4 >> 5, w4 = lin4 & 31;
        *(float4*)(dp + lin4 * 4) = *(const float4*)&s[tile * 132 + w4 * 4];
    }
}

__global__ __launch_bounds__(128) void permB_kernel(
    const float* __restrict__ s0, const float* __restrict__ s1,
    const float* __restrict__ s2, const float* __restrict__ s3,
    float* __restrict__ d0, float* __restrict__ d1,
    float* __restrict__ d2, float* __restrict__ d3)
{
    __shared__ float s[64 * 68];
    const int z = blockIdx.z;
    const float* src = (z == 0) ? s0 : (z == 1) ? s1 : (z == 2) ? s2 : s3;
    float* dst = (z == 0) ? d0 : (z == 1) ? d1 : (z == 2) ? d2 : d3;
    const int kc = blockIdx.x, nb = blockIdx.y;
    const int tid = threadIdx.x;
    const float* sp = src + (long long)nb * 128 * EE + kc * 32;
#pragma unroll
    for (int it = 0; it < 8; it++) {
        int idx = tid + it * 128;
        int r = idx >> 3, cq = idx & 7;
        float4 v = *(const float4*)(sp + (long long)r * EE + cq * 4);
        float b4[4] = {rna_tf32(v.x), rna_tf32(v.y), rna_tf32(v.z), rna_tf32(v.w)};
        int nt = r >> 3, rn = r & 7;
#pragma unroll
        for (int u = 0; u < 4; u++) {
            int kcc = cq * 4 + u;
            int kt = kcc >> 3, kk = kcc & 7;
            int lb = (rn << 2) | (kk & 3);
            int jb = (kk & 4) ? 1 : 0;
            s[(nt * 4 + kt) * 68 + lb * 2 + jb] = b4[u];
        }
    }
    __syncthreads();
    float* dp = dst + ((long long)nb * 32 + kc) * 4096;
#pragma unroll
    for (int j = 0; j < 8; j++) {
        int lin4 = tid + j * 128;
        int tile = lin4 >> 4, w4 = lin4 & 15;
        *(float4*)(dp + lin4 * 4) = *(const float4*)&s[tile * 68 + w4 * 4];
    }
}

// ---------------------------------------------------------------------------
// tf32 mma.sync GEMM on pre-permuted operands.
// MODE 0: fused QKV; epilogue writes FRAGMENT-MAJOR Q/K/V for attention.
// MODE 1: row-major + bias (o_proj).
// ---------------------------------------------------------------------------
#define GSM_FLOATS (4 * 4096 + 128)
#define GSM_BYTES  (GSM_FLOATS * 4)

template<int MODE>
__global__ __launch_bounds__(256) void mma_gemm2(
    const float* __restrict__ A,
    const float* __restrict__ W0, const float* __restrict__ W1, const float* __restrict__ W2,
    const float* __restrict__ b0, const float* __restrict__ b1, const float* __restrict__ b2,
    float* __restrict__ o0, float* __restrict__ o1, float* __restrict__ o2)
{
    extern __shared__ float gsm[];
    float* bA = gsm;               // [2][4096]
    float* bB = gsm + 8192;        // [2][4096]
    float* biasS = gsm + 16384;    // [128]

    const int tid = threadIdx.x;
    const int lane = tid & 31;
    const int wid = tid >> 5;
    const int wm = wid >> 2;
    const int wn = wid & 3;

    const int z = (MODE == 0) ? blockIdx.z : 0;
    const float* W    = (z == 0) ? W0 : (z == 1) ? W1 : W2;
    const float* bias = (z == 0) ? b0 : (z == 1) ? b1 : b2;

    const int nb = blockIdx.x, mb = blockIdx.y;
    const int m0 = mb * 128, n0 = nb * 128;
    if (tid < 128) biasS[tid] = bias[n0 + tid];

    const float* Ap = A + (long long)mb * 32 * 4096;
    const float* Wp = W + (long long)nb * 32 * 4096;

    float acc[4][4][4];
#pragma unroll
    for (int i = 0; i < 4; i++)
#pragma unroll
        for (int j = 0; j < 4; j++)
#pragma unroll
            for (int u = 0; u < 4; u++) acc[i][j][u] = 0.0f;

#pragma unroll
    for (int it = 0; it < 4; it++) {
        int off = tid * 4 + it * 1024;
        cp16(&bA[off], Ap + off);
        cp16(&bB[off], Wp + off);
    }
    cp_commit();

    for (int t = 0; t < 32; t++) {
        const int cur = t & 1;
        if (t + 1 < 32) {
            const float* As = Ap + (long long)(t + 1) * 4096;
            const float* Ws = Wp + (long long)(t + 1) * 4096;
            float* dA = bA + (cur ^ 1) * 4096;
            float* dB = bB + (cur ^ 1) * 4096;
#pragma unroll
            for (int it = 0; it < 4; it++) {
                int off = tid * 4 + it * 1024;
                cp16(dA + off, As + off);
                cp16(dB + off, Ws + off);
            }
            cp_commit();
            cp_wait<1>();
        } else {
            cp_wait<0>();
        }
        __syncthreads();

        const float* cA = bA + cur * 4096;
        const float* cB = bB + cur * 4096;
#pragma unroll
        for (int kt = 0; kt < 4; kt++) {
            uint4 afr[4];
            uint2 bfr[4];
#pragma unroll
            for (int i = 0; i < 4; i++)
                afr[i] = *(const uint4*)&cA[((wm * 4 + i) * 4 + kt) * 128 + lane * 4];
#pragma unroll
            for (int j = 0; j < 4; j++)
                bfr[j] = *(const uint2*)&cB[((wn * 4 + j) * 4 + kt) * 64 + lane * 2];
#pragma unroll
            for (int i = 0; i < 4; i++)
#pragma unroll
                for (int j = 0; j < 4; j++)
                    mma_tf32(acc[i][j], afr[i], bfr[j]);
        }
        __syncthreads();
    }

#pragma unroll
    for (int i = 0; i < 4; i++) {
        const int mrow = m0 + wm * 64 + i * 16 + (lane >> 2);
#pragma unroll
        for (int j = 0; j < 4; j++) {
            const int nn = wn * 32 + j * 8 + (lane & 3) * 2;
            const float bi0 = biasS[nn], bi1 = biasS[nn + 1];
            float v00 = acc[i][j][0] + bi0, v01 = acc[i][j][1] + bi1;  // row s
            float v10 = acc[i][j][2] + bi0, v11 = acc[i][j][3] + bi1;  // row s+8

            if (MODE == 1) {
                *(float2*)&o0[(long long)mrow * EE + n0 + nn]       = make_float2(v00, v01);
                *(float2*)&o0[(long long)(mrow + 8) * EE + n0 + nn] = make_float2(v10, v11);
            } else {
                const int n = n0 + nn;
                const int h = n >> 6;
                const int d = n & 63;           // even
                const int bq = mrow >> 11;
                const int s = mrow & 2047;      // s&8 == 0 here
                const long long hb = ((long long)(bq * HH + h)) * (SS * DD);
                if (z == 0) {
                    // Q A-fragment-major, pre-scaled
                    const int mt = (s >> 4) & 7;
                    const int la = ((s & 7) << 2) | (d & 3);
                    const int ja = (d & 4) ? 2 : 0;
                    long long adr = hb + (long long)(s >> 7) * 8192
                                  + (mt * 8 + (d >> 3)) * 128 + la * 4 + ja;
                    *(float2*)&o0[adr] = make_float2(rna_tf32(v00 * ATT_SCALE),
                                                     rna_tf32(v10 * ATT_SCALE));
                    *(float2*)&o0[adr + 4] = make_float2(rna_tf32(v01 * ATT_SCALE),
                                                         rna_tf32(v11 * ATT_SCALE));
                } else if (z == 1) {
                    // K B-fragment-major: tile (d8*8 + key8)*64; lb=((s&7)<<2)|(d&3)
                    const int nt = (s >> 3) & 7;
                    const int lb = ((s & 7) << 2) | (d & 3);
                    const int jb = (d & 4) ? 1 : 0;
                    long long adr = hb + (long long)(s >> 6) * 4096
                                  + ((d >> 3) * 8 + nt) * 64 + lb * 2 + jb;
                    o1[adr]      = rna_tf32(v00);
                    o1[adr + 2]  = rna_tf32(v01);   // d+1 -> lb+1
                    o1[adr + 64] = rna_tf32(v10);   // s+8 -> nt+1
                    o1[adr + 66] = rna_tf32(v11);
                } else {
                    // V B-fragment-major: tile (key8*8 + d8)*64; lb=((d&7)<<2)|(s&3)
                    const int kt = (s >> 3) & 7;
                    const int lb = ((d & 7) << 2) | (s & 3);
                    const int jb = (s & 4) ? 1 : 0;
                    long long adr = hb + (long long)(s >> 6) * 4096
                                  + (kt * 8 + (d >> 3)) * 64 + lb * 2 + jb;
                    o2[adr]       = rna_tf32(v00);
                    o2[adr + 8]   = rna_tf32(v01);  // d+1 -> lb+4
                    o2[adr + 512] = rna_tf32(v10);  // s+8 -> kt+1
                    o2[adr + 520] = rna_tf32(v11);
                }
            }
        }
    }
}

// ---------------------------------------------------------------------------
// Flash attention v5: 8 warps x 32 q-rows (AQ=256), fragment-major operands.
// Q resident in smem (A-frag layout, one bulk copy). K/V 64-key chunks
// (B-frag layout) double-buffered via cp.async.bulk. P staged A-frag-major.
// All hot-loop smem accesses are wide & conflict-free; no xor math.
// smem: Qs[16384] | Ps[16384] | Ks[2][4096] | Vs[2][4096]  = 192KB
// ---------------------------------------------------------------------------
#define AQ 256
#define ATTN_SMEM (49152 * 4)   // 192KB

__global__ __launch_bounds__(256, 1) void attn5_kernel(
    const float* __restrict__ Q, const float* __restrict__ K,
    const float* __restrict__ V, float* __restrict__ ctx)
{
    extern __shared__ float sm[];
    float* Qs = sm;              // [16384]
    float* Ps = sm + 16384;      // [16384]
    float* Ks = sm + 32768;      // [2][4096]
    float* Vs = sm + 40960;      // [2][4096]
    __shared__ __align__(8) ull fullbar[2];

    const int tid = threadIdx.x;
    const int lane = tid & 31;
    const int wq = tid >> 5;     // 0..7 -> rows wq*32..wq*32+31
    const int g = lane >> 2;     // 0..7
    const int a = lane & 3;      // 0..3
    const int bh = blockIdx.y;
    const int q0 = blockIdx.x * AQ;

    const float* Qg = Q + (long long)bh * SS * DD + (long long)q0 * DD;
    const float* Kg = K + (long long)bh * SS * DD;
    const float* Vg = V + (long long)bh * SS * DD;

    const uint32_t bar0 = smem_u32(&fullbar[0]);
    const uint32_t bar1 = smem_u32(&fullbar[1]);

    if (tid == 0) {
        mbar_init(bar0, 1);
        mbar_init(bar1, 1);
        mbar_expect(bar0, 65536 + 16384 + 16384);   // Q + K0 + V0
        bulk_g2s(smem_u32(Qs), Qg, 65536, bar0);
        bulk_g2s(smem_u32(Ks), Kg, 16384, bar0);
        bulk_g2s(smem_u32(Vs), Vg, 16384, bar0);
    }
    __syncthreads();
    mbar_wait(bar0, 0);

    // per-warp tile bases (tiles t16 = wq*2+tt, tt in {0,1})
    const int t16a = wq * 2, t16b = wq * 2 + 1;
    const int qbA = (t16a >> 3) * 8192 + (t16a & 7) * 8 * 128 + lane * 4;  // +ks*128
    const int qbB = (t16b >> 3) * 8192 + (t16b & 7) * 8 * 128 + lane * 4;
    const int pbA = t16a * 8 * 128 + lane * 4;                              // +ks*128
    const int pbB = t16b * 8 * 128 + lane * 4;
    // producer P-store base: la_p = (g<<2)|(2a&3), ja_p = (2a&4)?2:0
    const int pstA = t16a * 8 * 128 + (((g << 2) | ((2 * a) & 3)) * 4) + (((2 * a) & 4) ? 2 : 0);
    const int pstB = t16b * 8 * 128 + (((g << 2) | ((2 * a) & 3)) * 4) + (((2 * a) & 4) ? 2 : 0);

    float mrow[4], lrow[4];     // [tt*2 + half]
#pragma unroll
    for (int i = 0; i < 4; i++) { mrow[i] = -1e30f; lrow[i] = 0.f; }
    float Oac[2][8][4];
#pragma unroll
    for (int tt = 0; tt < 2; tt++)
#pragma unroll
        for (int nt = 0; nt < 8; nt++)
#pragma unroll
            for (int u = 0; u < 4; u++) Oac[tt][nt][u] = 0.f;

    const int NCH = SS / 64;   // 32
    for (int t = 0; t < NCH; t++) {
        const int cur = t & 1;
        if (tid == 0 && t + 1 < NCH) {
            const uint32_t nb = (cur ^ 1) ? bar1 : bar0;
            mbar_expect(nb, 32768);
            bulk_g2s(smem_u32(Ks + (cur ^ 1) * 4096), Kg + (long long)(t + 1) * 4096, 16384, nb);
            bulk_g2s(smem_u32(Vs + (cur ^ 1) * 4096), Vg + (long long)(t + 1) * 4096, 16384, nb);
        }
        if (t) mbar_wait(cur ? bar1 : bar0, (t >> 1) & 1);

        const float* Kb = Ks + cur * 4096;
        const float* Vb = Vs + cur * 4096;

        // ---- S = Q @ K^T : wide fragment loads, one K-frag feeds 2 MMAs ----
        float Sac[2][8][4];
#pragma unroll
        for (int tt = 0; tt < 2; tt++)
#pragma unroll
            for (int nt = 0; nt < 8; nt++)
#pragma unroll
                for (int u = 0; u < 4; u++) Sac[tt][nt][u] = 0.f;

#pragma unroll
        for (int ks = 0; ks < 8; ks++) {
            const uint4 qf0 = *(const uint4*)&Qs[qbA + ks * 128];
            const uint4 qf1 = *(const uint4*)&Qs[qbB + ks * 128];
#pragma unroll
            for (int nt = 0; nt < 8; nt++) {
                const uint2 kf = *(const uint2*)&Kb[(ks * 8 + nt) * 64 + lane * 2];
                mma_tf32(Sac[0][nt], qf0, kf);
                mma_tf32(Sac[1][nt], qf1, kf);
            }
        }

        // ---- online softmax per A-tile; P -> smem (A-frag layout) ----
#pragma unroll
        for (int tt = 0; tt < 2; tt++) {
            float mx0 = -1e30f, mx1 = -1e30f;
#pragma unroll
            for (int nt = 0; nt < 8; nt++) {
                mx0 = fmaxf(mx0, fmaxf(Sac[tt][nt][0], Sac[tt][nt][1]));
                mx1 = fmaxf(mx1, fmaxf(Sac[tt][nt][2], Sac[tt][nt][3]));
            }
#pragma unroll
            for (int off = 1; off < 4; off <<= 1) {
                mx0 = fmaxf(mx0, __shfl_xor_sync(0xFFFFFFFFu, mx0, off));
                mx1 = fmaxf(mx1, __shfl_xor_sync(0xFFFFFFFFu, mx1, off));
            }
            const float mn0 = fmaxf(mrow[tt*2+0], mx0);
            const float mn1 = fmaxf(mrow[tt*2+1], mx1);
            const float al0 = __expf(mrow[tt*2+0] - mn0);
            const float al1 = __expf(mrow[tt*2+1] - mn1);
            mrow[tt*2+0] = mn0; mrow[tt*2+1] = mn1;

            float rs0 = 0.f, rs1 = 0.f;
            const int pst = tt ? pstB : pstA;
#pragma unroll
            for (int nt = 0; nt < 8; nt++) {
                float p0 = rna_tf32(__expf(Sac[tt][nt][0] - mn0));  // row g,   kk=2a
                float p1 = rna_tf32(__expf(Sac[tt][nt][1] - mn0));  // row g,   kk=2a+1
                float p2 = rna_tf32(__expf(Sac[tt][nt][2] - mn1));  // row g+8, kk=2a
                float p3 = rna_tf32(__expf(Sac[tt][nt][3] - mn1));  // row g+8, kk=2a+1
                rs0 += p0 + p1;
                rs1 += p2 + p3;
                // (p0,p2) adjacent (ja, ja|1); (p1,p3) at +4 (la+1)
                *(float2*)&Ps[pst + nt * 128]     = make_float2(p0, p2);
                *(float2*)&Ps[pst + nt * 128 + 4] = make_float2(p1, p3);
            }
#pragma unroll
            for (int off = 1; off < 4; off <<= 1) {
                rs0 += __shfl_xor_sync(0xFFFFFFFFu, rs0, off);
                rs1 += __shfl_xor_sync(0xFFFFFFFFu, rs1, off);
            }
            lrow[tt*2+0] = lrow[tt*2+0] * al0 + rs0;
            lrow[tt*2+1] = lrow[tt*2+1] * al1 + rs1;
#pragma unroll
            for (int nt = 0; nt < 8; nt++) {
                Oac[tt][nt][0] *= al0; Oac[tt][nt][1] *= al0;
                Oac[tt][nt][2] *= al1; Oac[tt][nt][3] *= al1;
            }
        }
        __syncwarp();   // P stores (own warp tiles) visible to own-warp loads

        // ---- O += P @ V : LDS.128 P-frag + LDS.64 V-frag per 2 MMAs ----
#pragma unroll
        for (int ks = 0; ks < 8; ks++) {
            const uint4 pf0 = *(const uint4*)&Ps[pbA + ks * 128];
            const uint4 pf1 = *(const uint4*)&Ps[pbB + ks * 128];
#pragma unroll
            for (int nt = 0; nt < 8; nt++) {
                const uint2 vf = *(const uint2*)&Vb[(ks * 8 + nt) * 64 + lane * 2];
                mma_tf32(Oac[0][nt], pf0, vf);
                mma_tf32(Oac[1][nt], pf1, vf);
            }
        }
        __syncthreads();   // all warps done with K/V buffers before next refill
    }

    if (tid == 0) { mbar_inval(bar0); mbar_inval(bar1); }

    // ---- epilogue: normalize, tf32-round, write merged-head ctx ----
    const int b = bh / HH, h = bh % HH;
#pragma unroll
    for (int tt = 0; tt < 2; tt++) {
        const int r0g = q0 + wq * 32 + tt * 16 + g;
        const int r1g = r0g + 8;
        const float rl0 = 1.0f / lrow[tt*2+0], rl1 = 1.0f / lrow[tt*2+1];
#pragma unroll
        for (int nt = 0; nt < 8; nt++) {
            const int d = h * DD + nt * 8 + 2 * a;
            *(float2*)&ctx[(long long)(b * SS + r0g) * EE + d] =
                make_float2(rna_tf32(Oac[tt][nt][0] * rl0), rna_tf32(Oac[tt][nt][1] * rl0));
            *(float2*)&ctx[(long long)(b * SS + r1g) * EE + d] =
                make_float2(rna_tf32(Oac[tt][nt][2] * rl1), rna_tf32(Oac[tt][nt][3] * rl1));
        }
    }
}

// ---------------------------------------------------------------------------
extern "C" void kernel_launch(void* const* d_in, const int* in_sizes, int n_in,
                              void* d_out, int out_size)
{
    const float* x   = (const float*)d_in[0];
    const float* q_w = (const float*)d_in[1];
    const float* q_b = (const float*)d_in[2];
    const float* k_w = (const float*)d_in[3];
    const float* k_b = (const float*)d_in[4];
    const float* v_w = (const float*)d_in[5];
    const float* v_b = (const float*)d_in[6];
    const float* o_w = (const float*)d_in[7];
    const float* o_b = (const float*)d_in[8];
    float* out = (float*)d_out;

    float *qbuf, *kbuf, *vbuf, *cbuf, *xr, *wq, *wk, *wv, *wo;
    cudaGetSymbolAddress((void**)&qbuf, g_q);
    cudaGetSymbolAddress((void**)&kbuf, g_k);
    cudaGetSymbolAddress((void**)&vbuf, g_v);
    cudaGetSymbolAddress((void**)&cbuf, g_ctx);
    cudaGetSymbolAddress((void**)&xr, g_xr);
    cudaGetSymbolAddress((void**)&wq, g_wq);
    cudaGetSymbolAddress((void**)&wk, g_wk);
    cudaGetSymbolAddress((void**)&wv, g_wv);
    cudaGetSymbolAddress((void**)&wo, g_wo);

    cudaFuncSetAttribute(attn5_kernel, cudaFuncAttributeMaxDynamicSharedMemorySize,
                         ATTN_SMEM);
    cudaFuncSetAttribute(mma_gemm2<0>, cudaFuncAttributeMaxDynamicSharedMemorySize,
                         GSM_BYTES);
    cudaFuncSetAttribute(mma_gemm2<1>, cudaFuncAttributeMaxDynamicSharedMemorySize,
                         GSM_BYTES);

    // layout permutation + tf32 rounding
    dim3 pga(32, MTOK / 128);          // (32, 32)
    permA_kernel<<<pga, 128>>>(x, xr);
    dim3 pgb(32, EE / 128, 4);         // (32, 8, 4)
    permB_kernel<<<pgb, 128>>>(q_w, k_w, v_w, o_w, wq, wk, wv, wo);

    // fused QKV projections (epilogue writes fragment-major Q/K/V)
    dim3 qgrid(EE / 128, MTOK / 128, 3);
    mma_gemm2<0><<<qgrid, 256, GSM_BYTES>>>(xr, wq, wk, wv, q_b, k_b, v_b,
                                            qbuf, kbuf, vbuf);

    // flash attention
    dim3 agrid(SS / AQ, BHH);          // (8, 32)
    attn5_kernel<<<agrid, 256, ATTN_SMEM>>>(qbuf, kbuf, vbuf, cbuf);

    // permute ctx (reuse xr) then output projection
    permA_kernel<<<pga, 128>>>(cbuf, xr);
    dim3 ogrid(EE / 128, MTOK / 128, 1);
    mma_gemm2<1><<<ogrid, 256, GSM_BYTES>>>(xr, wo, nullptr, nullptr,
                                            o_b, nullptr, nullptr,
                                            out, nullptr, nullptr);
}

// round 13
// speedup vs baseline: 1.1080x; 1.1080x over previous
#include <cuda_runtime.h>
#include <cuda_bf16.h>
#include <math.h>
#include <stdint.h>

// Problem constants
#define BB 2
#define SS 2048
#define EE 1024
#define HH 16
#define DD 64
#define BHH (BB*HH)          // 32
#define MTOK (BB*SS)         // 4096
#define ATT_SCALE 0.125f     // 64^-0.5

typedef unsigned long long ull;

// Scratch (device globals — no allocs allowed)
// Q: per-bh A-fragment-major (128-row blocks of 8192 floats), pre-scaled, tf32
// K: per-bh B-fragment-major (64-key chunks of 4096 floats, tiles (d8*8+key8)*64)
// V: per-bh B-fragment-major (64-key chunks of 4096 floats, tiles (key8*8+d8)*64)
__device__ float g_q[(long long)BHH*SS*DD];
__device__ float g_k[(long long)BHH*SS*DD];
__device__ float g_v[(long long)BHH*SS*DD];
__device__ float g_ctx[(long long)MTOK*EE];   // attn out, row-major
__device__ float g_xr[(long long)MTOK*EE];    // permA(x); later permA(ctx)
__device__ float g_wq[(long long)EE*EE];      // permB(weights)
__device__ float g_wk[(long long)EE*EE];
__device__ float g_wv[(long long)EE*EE];
__device__ float g_wo[(long long)EE*EE];

// ---------------------------------------------------------------------------
// PTX helpers
// ---------------------------------------------------------------------------
__device__ __forceinline__ float rna_tf32(float x) {
    uint32_t r;
    asm("cvt.rna.tf32.f32 %0, %1;" : "=r"(r) : "f"(x));
    return __uint_as_float(r);
}
__device__ __forceinline__ uint32_t smem_u32(const void* p) {
    return (uint32_t)__cvta_generic_to_shared(p);
}
__device__ __forceinline__ void mbar_init(uint32_t a, uint32_t cnt) {
    asm volatile("mbarrier.init.shared.b64 [%0], %1;" :: "r"(a), "r"(cnt) : "memory");
}
__device__ __forceinline__ void mbar_inval(uint32_t a) {
    asm volatile("mbarrier.inval.shared.b64 [%0];" :: "r"(a) : "memory");
}
__device__ __forceinline__ void mbar_expect(uint32_t a, uint32_t bytes) {
    asm volatile("mbarrier.arrive.expect_tx.shared.b64 _, [%0], %1;"
                 :: "r"(a), "r"(bytes) : "memory");
}
__device__ __forceinline__ void mbar_wait(uint32_t a, uint32_t parity) {
    asm volatile(
        "{\n\t.reg .pred P;\n\t"
        "WL%=:\n\t"
        "mbarrier.try_wait.parity.acquire.cta.shared::cta.b64 P, [%0], %1, 0x989680;\n\t"
        "@!P bra WL%=;\n\t}"
        :: "r"(a), "r"(parity) : "memory");
}
__device__ __forceinline__ void bulk_g2s(uint32_t dst, const void* src,
                                         uint32_t bytes, uint32_t mbar) {
    asm volatile(
        "cp.async.bulk.shared::cluster.global.mbarrier::complete_tx::bytes "
        "[%0], [%1], %2, [%3];"
        :: "r"(dst), "l"(src), "r"(bytes), "r"(mbar) : "memory");
}
__device__ __forceinline__ void cp16(void* dst, const void* src) {
    unsigned d = (unsigned)__cvta_generic_to_shared(dst);
    asm volatile("cp.async.cg.shared.global [%0], [%1], 16;\n" :: "r"(d), "l"(src));
}
__device__ __forceinline__ void cp_commit() { asm volatile("cp.async.commit_group;\n"); }
template<int N> __device__ __forceinline__ void cp_wait() {
    asm volatile("cp.async.wait_group %0;\n" :: "n"(N) : "memory");
}
// warp-level tf32 MMA: D(16x8) += A(16x8) @ B(8x8), fp32 accum
__device__ __forceinline__ void mma_tf32(float* c, const uint4& a, const uint2& b) {
    asm volatile(
        "mma.sync.aligned.m16n8k8.row.col.f32.tf32.tf32.f32 "
        "{%0,%1,%2,%3}, {%4,%5,%6,%7}, {%8,%9}, {%0,%1,%2,%3};"
        : "+f"(c[0]), "+f"(c[1]), "+f"(c[2]), "+f"(c[3])
        : "r"(a.x), "r"(a.y), "r"(a.z), "r"(a.w), "r"(b.x), "r"(b.y));
}

// ---------------------------------------------------------------------------
// Layout permutation kernels (fused tf32 rounding) — unchanged.
// ---------------------------------------------------------------------------
__global__ __launch_bounds__(128) void permA_kernel(const float* __restrict__ src,
                                                    float* __restrict__ dst)
{
    __shared__ float s[32 * 132];
    const int kc = blockIdx.x, mb = blockIdx.y;
    const int tid = threadIdx.x;
    const float* sp = src + (long long)mb * 128 * EE + kc * 32;
#pragma unroll
    for (int it = 0; it < 8; it++) {
        int idx = tid + it * 128;
        int r = idx >> 3, cq = idx & 7;
        float4 v = *(const float4*)(sp + (long long)r * EE + cq * 4);
        float a4[4] = {rna_tf32(v.x), rna_tf32(v.y), rna_tf32(v.z), rna_tf32(v.w)};
        int mt = r >> 4, rm = r & 15;
#pragma unroll
        for (int u = 0; u < 4; u++) {
            int kcc = cq * 4 + u;
            int kt = kcc >> 3, kk = kcc & 7;
            int la = ((rm & 7) << 2) | (kk & 3);
            int ja = ((kk & 4) ? 2 : 0) | (rm >> 3);
            s[(mt * 4 + kt) * 132 + la * 4 + ja] = a4[u];
        }
    }
    __syncthreads();
    float* dp = dst + ((long long)mb * 32 + kc) * 4096;
#pragma unroll
    for (int j = 0; j < 8; j++) {
        int lin4 = tid + j * 128;
        int tile = lin4 >> 5, w4 = lin4 & 31;
        *(float4*)(dp + lin4 * 4) = *(const float4*)&s[tile * 132 + w4 * 4];
    }
}

__global__ __launch_bounds__(128) void permB_kernel(
    const float* __restrict__ s0, const float* __restrict__ s1,
    const float* __restrict__ s2, const float* __restrict__ s3,
    float* __restrict__ d0, float* __restrict__ d1,
    float* __restrict__ d2, float* __restrict__ d3)
{
    __shared__ float s[64 * 68];
    const int z = blockIdx.z;
    const float* src = (z == 0) ? s0 : (z == 1) ? s1 : (z == 2) ? s2 : s3;
    float* dst = (z == 0) ? d0 : (z == 1) ? d1 : (z == 2) ? d2 : d3;
    const int kc = blockIdx.x, nb = blockIdx.y;
    const int tid = threadIdx.x;
    const float* sp = src + (long long)nb * 128 * EE + kc * 32;
#pragma unroll
    for (int it = 0; it < 8; it++) {
        int idx = tid + it * 128;
        int r = idx >> 3, cq = idx & 7;
        float4 v = *(const float4*)(sp + (long long)r * EE + cq * 4);
        float b4[4] = {rna_tf32(v.x), rna_tf32(v.y), rna_tf32(v.z), rna_tf32(v.w)};
        int nt = r >> 3, rn = r & 7;
#pragma unroll
        for (int u = 0; u < 4; u++) {
            int kcc = cq * 4 + u;
            int kt = kcc >> 3, kk = kcc & 7;
            int lb = (rn << 2) | (kk & 3);
            int jb = (kk & 4) ? 1 : 0;
            s[(nt * 4 + kt) * 68 + lb * 2 + jb] = b4[u];
        }
    }
    __syncthreads();
    float* dp = dst + ((long long)nb * 32 + kc) * 4096;
#pragma unroll
    for (int j = 0; j < 8; j++) {
        int lin4 = tid + j * 128;
        int tile = lin4 >> 4, w4 = lin4 & 15;
        *(float4*)(dp + lin4 * 4) = *(const float4*)&s[tile * 68 + w4 * 4];
    }
}

// ---------------------------------------------------------------------------
// tf32 mma.sync GEMM on pre-permuted operands — unchanged from R12.
// ---------------------------------------------------------------------------
#define GSM_FLOATS (4 * 4096 + 128)
#define GSM_BYTES  (GSM_FLOATS * 4)

template<int MODE>
__global__ __launch_bounds__(256) void mma_gemm2(
    const float* __restrict__ A,
    const float* __restrict__ W0, const float* __restrict__ W1, const float* __restrict__ W2,
    const float* __restrict__ b0, const float* __restrict__ b1, const float* __restrict__ b2,
    float* __restrict__ o0, float* __restrict__ o1, float* __restrict__ o2)
{
    extern __shared__ float gsm[];
    float* bA = gsm;               // [2][4096]
    float* bB = gsm + 8192;        // [2][4096]
    float* biasS = gsm + 16384;    // [128]

    const int tid = threadIdx.x;
    const int lane = tid & 31;
    const int wid = tid >> 5;
    const int wm = wid >> 2;
    const int wn = wid & 3;

    const int z = (MODE == 0) ? blockIdx.z : 0;
    const float* W    = (z == 0) ? W0 : (z == 1) ? W1 : W2;
    const float* bias = (z == 0) ? b0 : (z == 1) ? b1 : b2;

    const int nb = blockIdx.x, mb = blockIdx.y;
    const int m0 = mb * 128, n0 = nb * 128;
    if (tid < 128) biasS[tid] = bias[n0 + tid];

    const float* Ap = A + (long long)mb * 32 * 4096;
    const float* Wp = W + (long long)nb * 32 * 4096;

    float acc[4][4][4];
#pragma unroll
    for (int i = 0; i < 4; i++)
#pragma unroll
        for (int j = 0; j < 4; j++)
#pragma unroll
            for (int u = 0; u < 4; u++) acc[i][j][u] = 0.0f;

#pragma unroll
    for (int it = 0; it < 4; it++) {
        int off = tid * 4 + it * 1024;
        cp16(&bA[off], Ap + off);
        cp16(&bB[off], Wp + off);
    }
    cp_commit();

    for (int t = 0; t < 32; t++) {
        const int cur = t & 1;
        if (t + 1 < 32) {
            const float* As = Ap + (long long)(t + 1) * 4096;
            const float* Ws = Wp + (long long)(t + 1) * 4096;
            float* dA = bA + (cur ^ 1) * 4096;
            float* dB = bB + (cur ^ 1) * 4096;
#pragma unroll
            for (int it = 0; it < 4; it++) {
                int off = tid * 4 + it * 1024;
                cp16(dA + off, As + off);
                cp16(dB + off, Ws + off);
            }
            cp_commit();
            cp_wait<1>();
        } else {
            cp_wait<0>();
        }
        __syncthreads();

        const float* cA = bA + cur * 4096;
        const float* cB = bB + cur * 4096;
#pragma unroll
        for (int kt = 0; kt < 4; kt++) {
            uint4 afr[4];
            uint2 bfr[4];
#pragma unroll
            for (int i = 0; i < 4; i++)
                afr[i] = *(const uint4*)&cA[((wm * 4 + i) * 4 + kt) * 128 + lane * 4];
#pragma unroll
            for (int j = 0; j < 4; j++)
                bfr[j] = *(const uint2*)&cB[((wn * 4 + j) * 4 + kt) * 64 + lane * 2];
#pragma unroll
            for (int i = 0; i < 4; i++)
#pragma unroll
                for (int j = 0; j < 4; j++)
                    mma_tf32(acc[i][j], afr[i], bfr[j]);
        }
        __syncthreads();
    }

#pragma unroll
    for (int i = 0; i < 4; i++) {
        const int mrow = m0 + wm * 64 + i * 16 + (lane >> 2);
#pragma unroll
        for (int j = 0; j < 4; j++) {
            const int nn = wn * 32 + j * 8 + (lane & 3) * 2;
            const float bi0 = biasS[nn], bi1 = biasS[nn + 1];
            float v00 = acc[i][j][0] + bi0, v01 = acc[i][j][1] + bi1;  // row s
            float v10 = acc[i][j][2] + bi0, v11 = acc[i][j][3] + bi1;  // row s+8

            if (MODE == 1) {
                *(float2*)&o0[(long long)mrow * EE + n0 + nn]       = make_float2(v00, v01);
                *(float2*)&o0[(long long)(mrow + 8) * EE + n0 + nn] = make_float2(v10, v11);
            } else {
                const int n = n0 + nn;
                const int h = n >> 6;
                const int d = n & 63;           // even
                const int bq = mrow >> 11;
                const int s = mrow & 2047;      // s&8 == 0 here
                const long long hb = ((long long)(bq * HH + h)) * (SS * DD);
                if (z == 0) {
                    const int mt = (s >> 4) & 7;
                    const int la = ((s & 7) << 2) | (d & 3);
                    const int ja = (d & 4) ? 2 : 0;
                    long long adr = hb + (long long)(s >> 7) * 8192
                                  + (mt * 8 + (d >> 3)) * 128 + la * 4 + ja;
                    *(float2*)&o0[adr] = make_float2(rna_tf32(v00 * ATT_SCALE),
                                                     rna_tf32(v10 * ATT_SCALE));
                    *(float2*)&o0[adr + 4] = make_float2(rna_tf32(v01 * ATT_SCALE),
                                                         rna_tf32(v11 * ATT_SCALE));
                } else if (z == 1) {
                    const int nt = (s >> 3) & 7;
                    const int lb = ((s & 7) << 2) | (d & 3);
                    const int jb = (d & 4) ? 1 : 0;
                    long long adr = hb + (long long)(s >> 6) * 4096
                                  + ((d >> 3) * 8 + nt) * 64 + lb * 2 + jb;
                    o1[adr]      = rna_tf32(v00);
                    o1[adr + 2]  = rna_tf32(v01);
                    o1[adr + 64] = rna_tf32(v10);
                    o1[adr + 66] = rna_tf32(v11);
                } else {
                    const int kt = (s >> 3) & 7;
                    const int lb = ((d & 7) << 2) | (s & 3);
                    const int jb = (s & 4) ? 1 : 0;
                    long long adr = hb + (long long)(s >> 6) * 4096
                                  + (kt * 8 + (d >> 3)) * 64 + lb * 2 + jb;
                    o2[adr]       = rna_tf32(v00);
                    o2[adr + 8]   = rna_tf32(v01);
                    o2[adr + 512] = rna_tf32(v10);
                    o2[adr + 520] = rna_tf32(v11);
                }
            }
        }
    }
}

// ---------------------------------------------------------------------------
// Flash attention v6: AQ=128, 4 warps, 96KB smem -> 2 CTAs/SM so one CTA's
// softmax overlaps the other's MMA. Single K/V buffers refilled in-phase:
//   K(t+1) copy issued after QK(t) (hides under PV(t)),
//   V(t+1) copy issued after PV(t) (hides under QK(t+1)).
// smem: Qs[8192] | Ps[8192] | Ks[4096] | Vs[4096] = 96KB
// ---------------------------------------------------------------------------
#define AQ 128
#define ATTN_SMEM (24576 * 4)   // 96KB

__global__ __launch_bounds__(128) void attn6_kernel(
    const float* __restrict__ Q, const float* __restrict__ K,
    const float* __restrict__ V, float* __restrict__ ctx)
{
    extern __shared__ float sm[];
    float* Qs = sm;              // [8192]  A-frag-major Q block
    float* Ps = sm + 8192;       // [8192]  A-frag-major P
    float* Ks = sm + 16384;      // [4096]  B-frag-major K chunk
    float* Vs = sm + 20480;      // [4096]  B-frag-major V chunk
    __shared__ __align__(8) ull bars[2];

    const int tid = threadIdx.x;
    const int lane = tid & 31;
    const int wq = tid >> 5;     // 0..3 -> rows wq*32..wq*32+31
    const int g = lane >> 2;     // 0..7
    const int a = lane & 3;      // 0..3
    const int bh = blockIdx.y;
    const int q0 = blockIdx.x * AQ;

    const float* Qg = Q + (long long)bh * SS * DD + (long long)q0 * DD;
    const float* Kg = K + (long long)bh * SS * DD;
    const float* Vg = V + (long long)bh * SS * DD;

    const uint32_t kbar = smem_u32(&bars[0]);
    const uint32_t vbar = smem_u32(&bars[1]);

    if (tid == 0) {
        mbar_init(kbar, 1);
        mbar_init(vbar, 1);
        mbar_expect(kbar, 32768 + 16384);   // Q + K0
        bulk_g2s(smem_u32(Qs), Qg, 32768, kbar);
        bulk_g2s(smem_u32(Ks), Kg, 16384, kbar);
        mbar_expect(vbar, 16384);           // V0
        bulk_g2s(smem_u32(Vs), Vg, 16384, vbar);
    }
    __syncthreads();

    // per-warp tile bases (tiles t16 = wq*2+tt, tt in {0,1}; t16 in 0..7)
    const int t16a = wq * 2, t16b = wq * 2 + 1;
    const int qbA = t16a * 1024 + lane * 4;   // + ks*128
    const int qbB = t16b * 1024 + lane * 4;
    const int pbA = t16a * 1024 + lane * 4;
    const int pbB = t16b * 1024 + lane * 4;
    const int pstA = t16a * 1024 + (((g << 2) | ((2 * a) & 3)) * 4) + (((2 * a) & 4) ? 2 : 0);
    const int pstB = t16b * 1024 + (((g << 2) | ((2 * a) & 3)) * 4) + (((2 * a) & 4) ? 2 : 0);

    float mrow[4], lrow[4];     // [tt*2 + half]
#pragma unroll
    for (int i = 0; i < 4; i++) { mrow[i] = -1e30f; lrow[i] = 0.f; }
    float Oac[2][8][4];
#pragma unroll
    for (int tt = 0; tt < 2; tt++)
#pragma unroll
        for (int nt = 0; nt < 8; nt++)
#pragma unroll
            for (int u = 0; u < 4; u++) Oac[tt][nt][u] = 0.f;

    const int NCH = SS / 64;   // 32
    for (int t = 0; t < NCH; t++) {
        // ---- wait K(t) (and Q on t=0) ----
        mbar_wait(kbar, t & 1);

        // ---- S = Q @ K^T ----
        float Sac[2][8][4];
#pragma unroll
        for (int tt = 0; tt < 2; tt++)
#pragma unroll
            for (int nt = 0; nt < 8; nt++)
#pragma unroll
                for (int u = 0; u < 4; u++) Sac[tt][nt][u] = 0.f;

#pragma unroll
        for (int ks = 0; ks < 8; ks++) {
            const uint4 qf0 = *(const uint4*)&Qs[qbA + ks * 128];
            const uint4 qf1 = *(const uint4*)&Qs[qbB + ks * 128];
#pragma unroll
            for (int nt = 0; nt < 8; nt++) {
                const uint2 kf = *(const uint2*)&Ks[(ks * 8 + nt) * 64 + lane * 2];
                mma_tf32(Sac[0][nt], qf0, kf);
                mma_tf32(Sac[1][nt], qf1, kf);
            }
        }

        // all warps done reading Ks -> refill with K(t+1), overlaps softmax+PV
        __syncthreads();
        if (tid == 0 && t + 1 < NCH) {
            mbar_expect(kbar, 16384);
            bulk_g2s(smem_u32(Ks), Kg + (long long)(t + 1) * 4096, 16384, kbar);
        }

        // ---- online softmax per A-tile; P -> smem (A-frag layout) ----
#pragma unroll
        for (int tt = 0; tt < 2; tt++) {
            float mx0 = -1e30f, mx1 = -1e30f;
#pragma unroll
            for (int nt = 0; nt < 8; nt++) {
                mx0 = fmaxf(mx0, fmaxf(Sac[tt][nt][0], Sac[tt][nt][1]));
                mx1 = fmaxf(mx1, fmaxf(Sac[tt][nt][2], Sac[tt][nt][3]));
            }
#pragma unroll
            for (int off = 1; off < 4; off <<= 1) {
                mx0 = fmaxf(mx0, __shfl_xor_sync(0xFFFFFFFFu, mx0, off));
                mx1 = fmaxf(mx1, __shfl_xor_sync(0xFFFFFFFFu, mx1, off));
            }
            const float mn0 = fmaxf(mrow[tt*2+0], mx0);
            const float mn1 = fmaxf(mrow[tt*2+1], mx1);
            const float al0 = __expf(mrow[tt*2+0] - mn0);
            const float al1 = __expf(mrow[tt*2+1] - mn1);
            mrow[tt*2+0] = mn0; mrow[tt*2+1] = mn1;

            float rs0 = 0.f, rs1 = 0.f;
            const int pst = tt ? pstB : pstA;
#pragma unroll
            for (int nt = 0; nt < 8; nt++) {
                float p0 = __expf(Sac[tt][nt][0] - mn0);
                float p1 = __expf(Sac[tt][nt][1] - mn0);
                float p2 = __expf(Sac[tt][nt][2] - mn1);
                float p3 = __expf(Sac[tt][nt][3] - mn1);
                rs0 += p0 + p1;
                rs1 += p2 + p3;
                *(float2*)&Ps[pst + nt * 128]     = make_float2(p0, p2);
                *(float2*)&Ps[pst + nt * 128 + 4] = make_float2(p1, p3);
            }
#pragma unroll
            for (int off = 1; off < 4; off <<= 1) {
                rs0 += __shfl_xor_sync(0xFFFFFFFFu, rs0, off);
                rs1 += __shfl_xor_sync(0xFFFFFFFFu, rs1, off);
            }
            lrow[tt*2+0] = lrow[tt*2+0] * al0 + rs0;
            lrow[tt*2+1] = lrow[tt*2+1] * al1 + rs1;
#pragma unroll
            for (int nt = 0; nt < 8; nt++) {
                Oac[tt][nt][0] *= al0; Oac[tt][nt][1] *= al0;
                Oac[tt][nt][2] *= al1; Oac[tt][nt][3] *= al1;
            }
        }
        __syncwarp();   // own-warp P stores visible to own-warp loads

        // ---- wait V(t), then O += P @ V ----
        mbar_wait(vbar, t & 1);
#pragma unroll
        for (int ks = 0; ks < 8; ks++) {
            const uint4 pf0 = *(const uint4*)&Ps[pbA + ks * 128];
            const uint4 pf1 = *(const uint4*)&Ps[pbB + ks * 128];
#pragma unroll
            for (int nt = 0; nt < 8; nt++) {
                const uint2 vf = *(const uint2*)&Vs[(ks * 8 + nt) * 64 + lane * 2];
                mma_tf32(Oac[0][nt], pf0, vf);
                mma_tf32(Oac[1][nt], pf1, vf);
            }
        }

        // all warps done reading Vs -> refill with V(t+1), overlaps next QK
        __syncthreads();
        if (tid == 0 && t + 1 < NCH) {
            mbar_expect(vbar, 16384);
            bulk_g2s(smem_u32(Vs), Vg + (long long)(t + 1) * 4096, 16384, vbar);
        }
    }

    __syncthreads();
    if (tid == 0) { mbar_inval(kbar); mbar_inval(vbar); }

    // ---- epilogue: normalize, write merged-head ctx (permA rounds later) ----
    const int b = bh / HH, h = bh % HH;
#pragma unroll
    for (int tt = 0; tt < 2; tt++) {
        const int r0g = q0 + wq * 32 + tt * 16 + g;
        const int r1g = r0g + 8;
        const float rl0 = 1.0f / lrow[tt*2+0], rl1 = 1.0f / lrow[tt*2+1];
#pragma unroll
        for (int nt = 0; nt < 8; nt++) {
            const int d = h * DD + nt * 8 + 2 * a;
            *(float2*)&ctx[(long long)(b * SS + r0g) * EE + d] =
                make_float2(Oac[tt][nt][0] * rl0, Oac[tt][nt][1] * rl0);
            *(float2*)&ctx[(long long)(b * SS + r1g) * EE + d] =
                make_float2(Oac[tt][nt][2] * rl1, Oac[tt][nt][3] * rl1);
        }
    }
}

// ---------------------------------------------------------------------------
extern "C" void kernel_launch(void* const* d_in, const int* in_sizes, int n_in,
                              void* d_out, int out_size)
{
    const float* x   = (const float*)d_in[0];
    const float* q_w = (const float*)d_in[1];
    const float* q_b = (const float*)d_in[2];
    const float* k_w = (const float*)d_in[3];
    const float* k_b = (const float*)d_in[4];
    const float* v_w = (const float*)d_in[5];
    const float* v_b = (const float*)d_in[6];
    const float* o_w = (const float*)d_in[7];
    const float* o_b = (const float*)d_in[8];
    float* out = (float*)d_out;

    float *qbuf, *kbuf, *vbuf, *cbuf, *xr, *wq, *wk, *wv, *wo;
    cudaGetSymbolAddress((void**)&qbuf, g_q);
    cudaGetSymbolAddress((void**)&kbuf, g_k);
    cudaGetSymbolAddress((void**)&vbuf, g_v);
    cudaGetSymbolAddress((void**)&cbuf, g_ctx);
    cudaGetSymbolAddress((void**)&xr, g_xr);
    cudaGetSymbolAddress((void**)&wq, g_wq);
    cudaGetSymbolAddress((void**)&wk, g_wk);
    cudaGetSymbolAddress((void**)&wv, g_wv);
    cudaGetSymbolAddress((void**)&wo, g_wo);

    cudaFuncSetAttribute(attn6_kernel, cudaFuncAttributeMaxDynamicSharedMemorySize,
                         ATTN_SMEM);
    cudaFuncSetAttribute(mma_gemm2<0>, cudaFuncAttributeMaxDynamicSharedMemorySize,
                         GSM_BYTES);
    cudaFuncSetAttribute(mma_gemm2<1>, cudaFuncAttributeMaxDynamicSharedMemorySize,
                         GSM_BYTES);

    // layout permutation + tf32 rounding
    dim3 pga(32, MTOK / 128);          // (32, 32)
    permA_kernel<<<pga, 128>>>(x, xr);
    dim3 pgb(32, EE / 128, 4);         // (32, 8, 4)
    permB_kernel<<<pgb, 128>>>(q_w, k_w, v_w, o_w, wq, wk, wv, wo);

    // fused QKV projections (epilogue writes fragment-major Q/K/V)
    dim3 qgrid(EE / 128, MTOK / 128, 3);
    mma_gemm2<0><<<qgrid, 256, GSM_BYTES>>>(xr, wq, wk, wv, q_b, k_b, v_b,
                                            qbuf, kbuf, vbuf);

    // flash attention (2 CTAs/SM ping-pong)
    dim3 agrid(SS / AQ, BHH);          // (16, 32)
    attn6_kernel<<<agrid, 128, ATTN_SMEM>>>(qbuf, kbuf, vbuf, cbuf);

    // permute ctx (reuse xr) then output projection
    permA_kernel<<<pga, 128>>>(cbuf, xr);
    dim3 ogrid(EE / 128, MTOK / 128, 1);
    mma_gemm2<1><<<ogrid, 256, GSM_BYTES>>>(xr, wo, nullptr, nullptr,
                                            o_b, nullptr, nullptr,
                                            out, nullptr, nullptr);
}

// round 14
// speedup vs baseline: 1.1775x; 1.0627x over previous
#include <cuda_runtime.h>
#include <cuda_bf16.h>
#include <math.h>
#include <stdint.h>

// Problem constants
#define BB 2
#define SS 2048
#define EE 1024
#define HH 16
#define DD 64
#define BHH (BB*HH)          // 32
#define MTOK (BB*SS)         // 4096
#define ATT_SCALE 0.125f     // 64^-0.5

typedef unsigned long long ull;

// Scratch (device globals — no allocs allowed)
// Q: per-bh A-fragment-major (128-row blocks of 8192 floats), pre-scaled, tf32
// K: per-bh B-fragment-major 64-key chunks; keys PERMUTED within each 8-group
//    by sigma(x) = (x&3)*2 + (x>>2)  (so S C-frags are PV A-frags verbatim)
// V: per-bh B-fragment-major 64-key chunks, natural key order
__device__ float g_q[(long long)BHH*SS*DD];
__device__ float g_k[(long long)BHH*SS*DD];
__device__ float g_v[(long long)BHH*SS*DD];
__device__ float g_xr[(long long)MTOK*EE];    // permA(x); later attn O (A-frag-major)
__device__ float g_wq[(long long)EE*EE];      // permB(weights)
__device__ float g_wk[(long long)EE*EE];
__device__ float g_wv[(long long)EE*EE];
__device__ float g_wo[(long long)EE*EE];

// ---------------------------------------------------------------------------
// PTX helpers
// ---------------------------------------------------------------------------
__device__ __forceinline__ float rna_tf32(float x) {
    uint32_t r;
    asm("cvt.rna.tf32.f32 %0, %1;" : "=r"(r) : "f"(x));
    return __uint_as_float(r);
}
__device__ __forceinline__ uint32_t smem_u32(const void* p) {
    return (uint32_t)__cvta_generic_to_shared(p);
}
__device__ __forceinline__ void mbar_init(uint32_t a, uint32_t cnt) {
    asm volatile("mbarrier.init.shared.b64 [%0], %1;" :: "r"(a), "r"(cnt) : "memory");
}
__device__ __forceinline__ void mbar_inval(uint32_t a) {
    asm volatile("mbarrier.inval.shared.b64 [%0];" :: "r"(a) : "memory");
}
__device__ __forceinline__ void mbar_expect(uint32_t a, uint32_t bytes) {
    asm volatile("mbarrier.arrive.expect_tx.shared.b64 _, [%0], %1;"
                 :: "r"(a), "r"(bytes) : "memory");
}
__device__ __forceinline__ void mbar_wait(uint32_t a, uint32_t parity) {
    asm volatile(
        "{\n\t.reg .pred P;\n\t"
        "WL%=:\n\t"
        "mbarrier.try_wait.parity.acquire.cta.shared::cta.b64 P, [%0], %1, 0x989680;\n\t"
        "@!P bra WL%=;\n\t}"
        :: "r"(a), "r"(parity) : "memory");
}
__device__ __forceinline__ void bulk_g2s(uint32_t dst, const void* src,
                                         uint32_t bytes, uint32_t mbar) {
    asm volatile(
        "cp.async.bulk.shared::cluster.global.mbarrier::complete_tx::bytes "
        "[%0], [%1], %2, [%3];"
        :: "r"(dst), "l"(src), "r"(bytes), "r"(mbar) : "memory");
}
__device__ __forceinline__ void cp16(void* dst, const void* src) {
    unsigned d = (unsigned)__cvta_generic_to_shared(dst);
    asm volatile("cp.async.cg.shared.global [%0], [%1], 16;\n" :: "r"(d), "l"(src));
}
__device__ __forceinline__ void cp_commit() { asm volatile("cp.async.commit_group;\n"); }
template<int N> __device__ __forceinline__ void cp_wait() {
    asm volatile("cp.async.wait_group %0;\n" :: "n"(N) : "memory");
}
// warp-level tf32 MMA: D(16x8) += A(16x8) @ B(8x8), fp32 accum
__device__ __forceinline__ void mma_tf32(float* c, const uint4& a, const uint2& b) {
    asm volatile(
        "mma.sync.aligned.m16n8k8.row.col.f32.tf32.tf32.f32 "
        "{%0,%1,%2,%3}, {%4,%5,%6,%7}, {%8,%9}, {%0,%1,%2,%3};"
        : "+f"(c[0]), "+f"(c[1]), "+f"(c[2]), "+f"(c[3])
        : "r"(a.x), "r"(a.y), "r"(a.z), "r"(a.w), "r"(b.x), "r"(b.y));
}

// ---------------------------------------------------------------------------
// Layout permutation kernels (fused tf32 rounding) — unchanged.
// ---------------------------------------------------------------------------
__global__ __launch_bounds__(128) void permA_kernel(const float* __restrict__ src,
                                                    float* __restrict__ dst)
{
    __shared__ float s[32 * 132];
    const int kc = blockIdx.x, mb = blockIdx.y;
    const int tid = threadIdx.x;
    const float* sp = src + (long long)mb * 128 * EE + kc * 32;
#pragma unroll
    for (int it = 0; it < 8; it++) {
        int idx = tid + it * 128;
        int r = idx >> 3, cq = idx & 7;
        float4 v = *(const float4*)(sp + (long long)r * EE + cq * 4);
        float a4[4] = {rna_tf32(v.x), rna_tf32(v.y), rna_tf32(v.z), rna_tf32(v.w)};
        int mt = r >> 4, rm = r & 15;
#pragma unroll
        for (int u = 0; u < 4; u++) {
            int kcc = cq * 4 + u;
            int kt = kcc >> 3, kk = kcc & 7;
            int la = ((rm & 7) << 2) | (kk & 3);
            int ja = ((kk & 4) ? 2 : 0) | (rm >> 3);
            s[(mt * 4 + kt) * 132 + la * 4 + ja] = a4[u];
        }
    }
    __syncthreads();
    float* dp = dst + ((long long)mb * 32 + kc) * 4096;
#pragma unroll
    for (int j = 0; j < 8; j++) {
        int lin4 = tid + j * 128;
        int tile = lin4 >> 5, w4 = lin4 & 31;
        *(float4*)(dp + lin4 * 4) = *(const float4*)&s[tile * 132 + w4 * 4];
    }
}

__global__ __launch_bounds__(128) void permB_kernel(
    const float* __restrict__ s0, const float* __restrict__ s1,
    const float* __restrict__ s2, const float* __restrict__ s3,
    float* __restrict__ d0, float* __restrict__ d1,
    float* __restrict__ d2, float* __restrict__ d3)
{
    __shared__ float s[64 * 68];
    const int z = blockIdx.z;
    const float* src = (z == 0) ? s0 : (z == 1) ? s1 : (z == 2) ? s2 : s3;
    float* dst = (z == 0) ? d0 : (z == 1) ? d1 : (z == 2) ? d2 : d3;
    const int kc = blockIdx.x, nb = blockIdx.y;
    const int tid = threadIdx.x;
    const float* sp = src + (long long)nb * 128 * EE + kc * 32;
#pragma unroll
    for (int it = 0; it < 8; it++) {
        int idx = tid + it * 128;
        int r = idx >> 3, cq = idx & 7;
        float4 v = *(const float4*)(sp + (long long)r * EE + cq * 4);
        float b4[4] = {rna_tf32(v.x), rna_tf32(v.y), rna_tf32(v.z), rna_tf32(v.w)};
        int nt = r >> 3, rn = r & 7;
#pragma unroll
        for (int u = 0; u < 4; u++) {
            int kcc = cq * 4 + u;
            int kt = kcc >> 3, kk = kcc & 7;
            int lb = (rn << 2) | (kk & 3);
            int jb = (kk & 4) ? 1 : 0;
            s[(nt * 4 + kt) * 68 + lb * 2 + jb] = b4[u];
        }
    }
    __syncthreads();
    float* dp = dst + ((long long)nb * 32 + kc) * 4096;
#pragma unroll
    for (int j = 0; j < 8; j++) {
        int lin4 = tid + j * 128;
        int tile = lin4 >> 4, w4 = lin4 & 15;
        *(float4*)(dp + lin4 * 4) = *(const float4*)&s[tile * 68 + w4 * 4];
    }
}

// ---------------------------------------------------------------------------
// tf32 mma.sync GEMM on pre-permuted operands.
// MODE 0: fused QKV; K epilogue applies the key permutation sigma.
// MODE 1: row-major + bias (o_proj).
// ---------------------------------------------------------------------------
#define GSM_FLOATS (4 * 4096 + 128)
#define GSM_BYTES  (GSM_FLOATS * 4)

template<int MODE>
__global__ __launch_bounds__(256) void mma_gemm2(
    const float* __restrict__ A,
    const float* __restrict__ W0, const float* __restrict__ W1, const float* __restrict__ W2,
    const float* __restrict__ b0, const float* __restrict__ b1, const float* __restrict__ b2,
    float* __restrict__ o0, float* __restrict__ o1, float* __restrict__ o2)
{
    extern __shared__ float gsm[];
    float* bA = gsm;               // [2][4096]
    float* bB = gsm + 8192;        // [2][4096]
    float* biasS = gsm + 16384;    // [128]

    const int tid = threadIdx.x;
    const int lane = tid & 31;
    const int wid = tid >> 5;
    const int wm = wid >> 2;
    const int wn = wid & 3;

    const int z = (MODE == 0) ? blockIdx.z : 0;
    const float* W    = (z == 0) ? W0 : (z == 1) ? W1 : W2;
    const float* bias = (z == 0) ? b0 : (z == 1) ? b1 : b2;

    const int nb = blockIdx.x, mb = blockIdx.y;
    const int m0 = mb * 128, n0 = nb * 128;
    if (tid < 128) biasS[tid] = bias[n0 + tid];

    const float* Ap = A + (long long)mb * 32 * 4096;
    const float* Wp = W + (long long)nb * 32 * 4096;

    float acc[4][4][4];
#pragma unroll
    for (int i = 0; i < 4; i++)
#pragma unroll
        for (int j = 0; j < 4; j++)
#pragma unroll
            for (int u = 0; u < 4; u++) acc[i][j][u] = 0.0f;

#pragma unroll
    for (int it = 0; it < 4; it++) {
        int off = tid * 4 + it * 1024;
        cp16(&bA[off], Ap + off);
        cp16(&bB[off], Wp + off);
    }
    cp_commit();

    for (int t = 0; t < 32; t++) {
        const int cur = t & 1;
        if (t + 1 < 32) {
            const float* As = Ap + (long long)(t + 1) * 4096;
            const float* Ws = Wp + (long long)(t + 1) * 4096;
            float* dA = bA + (cur ^ 1) * 4096;
            float* dB = bB + (cur ^ 1) * 4096;
#pragma unroll
            for (int it = 0; it < 4; it++) {
                int off = tid * 4 + it * 1024;
                cp16(dA + off, As + off);
                cp16(dB + off, Ws + off);
            }
            cp_commit();
            cp_wait<1>();
        } else {
            cp_wait<0>();
        }
        __syncthreads();

        const float* cA = bA + cur * 4096;
        const float* cB = bB + cur * 4096;
#pragma unroll
        for (int kt = 0; kt < 4; kt++) {
            uint4 afr[4];
            uint2 bfr[4];
#pragma unroll
            for (int i = 0; i < 4; i++)
                afr[i] = *(const uint4*)&cA[((wm * 4 + i) * 4 + kt) * 128 + lane * 4];
#pragma unroll
            for (int j = 0; j < 4; j++)
                bfr[j] = *(const uint2*)&cB[((wn * 4 + j) * 4 + kt) * 64 + lane * 2];
#pragma unroll
            for (int i = 0; i < 4; i++)
#pragma unroll
                for (int j = 0; j < 4; j++)
                    mma_tf32(acc[i][j], afr[i], bfr[j]);
        }
        __syncthreads();
    }

#pragma unroll
    for (int i = 0; i < 4; i++) {
        const int mrow = m0 + wm * 64 + i * 16 + (lane >> 2);
#pragma unroll
        for (int j = 0; j < 4; j++) {
            const int nn = wn * 32 + j * 8 + (lane & 3) * 2;
            const float bi0 = biasS[nn], bi1 = biasS[nn + 1];
            float v00 = acc[i][j][0] + bi0, v01 = acc[i][j][1] + bi1;  // row s
            float v10 = acc[i][j][2] + bi0, v11 = acc[i][j][3] + bi1;  // row s+8

            if (MODE == 1) {
                *(float2*)&o0[(long long)mrow * EE + n0 + nn]       = make_float2(v00, v01);
                *(float2*)&o0[(long long)(mrow + 8) * EE + n0 + nn] = make_float2(v10, v11);
            } else {
                const int n = n0 + nn;
                const int h = n >> 6;
                const int d = n & 63;           // even
                const int bq = mrow >> 11;
                const int s = mrow & 2047;      // s&8 == 0 here
                const long long hb = ((long long)(bq * HH + h)) * (SS * DD);
                if (z == 0) {
                    const int mt = (s >> 4) & 7;
                    const int la = ((s & 7) << 2) | (d & 3);
                    const int ja = (d & 4) ? 2 : 0;
                    long long adr = hb + (long long)(s >> 7) * 8192
                                  + (mt * 8 + (d >> 3)) * 128 + la * 4 + ja;
                    *(float2*)&o0[adr] = make_float2(rna_tf32(v00 * ATT_SCALE),
                                                     rna_tf32(v10 * ATT_SCALE));
                    *(float2*)&o0[adr + 4] = make_float2(rna_tf32(v01 * ATT_SCALE),
                                                         rna_tf32(v11 * ATT_SCALE));
                } else if (z == 1) {
                    // K: key permutation sigma(x) = (x&3)*2 + (x>>2) within 8-group
                    const int nt = (s >> 3) & 7;
                    const int sp = ((s & 3) << 1) | ((s & 4) >> 2);
                    const int lb = (sp << 2) | (d & 3);
                    const int jb = (d & 4) ? 1 : 0;
                    long long adr = hb + (long long)(s >> 6) * 4096
                                  + ((d >> 3) * 8 + nt) * 64 + lb * 2 + jb;
                    o1[adr]      = rna_tf32(v00);
                    o1[adr + 2]  = rna_tf32(v01);   // d+1 -> lb+1
                    o1[adr + 64] = rna_tf32(v10);   // s+8 -> nt+1, same sp
                    o1[adr + 66] = rna_tf32(v11);
                } else {
                    const int kt = (s >> 3) & 7;
                    const int lb = ((d & 7) << 2) | (s & 3);
                    const int jb = (s & 4) ? 1 : 0;
                    long long adr = hb + (long long)(s >> 6) * 4096
                                  + (kt * 8 + (d >> 3)) * 64 + lb * 2 + jb;
                    o2[adr]       = rna_tf32(v00);
                    o2[adr + 8]   = rna_tf32(v01);
                    o2[adr + 512] = rna_tf32(v10);
                    o2[adr + 520] = rna_tf32(v11);
                }
            }
        }
    }
}

// ---------------------------------------------------------------------------
// Flash attention v7: AQ=128, 4 warps. P stays in REGISTERS (key-permuted K
// makes S C-frags valid PV A-frags). No Ps smem. O written A-frag-major
// straight into g_xr for o_proj (no permA(ctx) pass).
// smem: Qs[8192] | Ks[4096] | Vs[4096] = 64KB -> 2+ CTAs/SM
// ---------------------------------------------------------------------------
#define AQ 128
#define ATTN_SMEM (16384 * 4)   // 64KB

__global__ __launch_bounds__(128) void attn7_kernel(
    const float* __restrict__ Q, const float* __restrict__ K,
    const float* __restrict__ V, float* __restrict__ xr)
{
    extern __shared__ float sm[];
    float* Qs = sm;              // [8192]  A-frag-major Q block
    float* Ks = sm + 8192;       // [4096]  B-frag-major K chunk (keys sigma-permuted)
    float* Vs = sm + 12288;      // [4096]  B-frag-major V chunk
    __shared__ __align__(8) ull bars[2];

    const int tid = threadIdx.x;
    const int lane = tid & 31;
    const int wq = tid >> 5;     // 0..3 -> rows wq*32..wq*32+31
    const int g = lane >> 2;     // 0..7
    const int a = lane & 3;      // 0..3
    const int bh = blockIdx.y;
    const int q0 = blockIdx.x * AQ;

    const float* Qg = Q + (long long)bh * SS * DD + (long long)q0 * DD;
    const float* Kg = K + (long long)bh * SS * DD;
    const float* Vg = V + (long long)bh * SS * DD;

    const uint32_t kbar = smem_u32(&bars[0]);
    const uint32_t vbar = smem_u32(&bars[1]);

    if (tid == 0) {
        mbar_init(kbar, 1);
        mbar_init(vbar, 1);
        mbar_expect(kbar, 32768 + 16384);   // Q + K0
        bulk_g2s(smem_u32(Qs), Qg, 32768, kbar);
        bulk_g2s(smem_u32(Ks), Kg, 16384, kbar);
        mbar_expect(vbar, 16384);           // V0
        bulk_g2s(smem_u32(Vs), Vg, 16384, vbar);
    }
    __syncthreads();

    // per-warp tile bases (tiles t16 = wq*2+tt)
    const int t16a = wq * 2, t16b = wq * 2 + 1;
    const int qbA = t16a * 1024 + lane * 4;   // + ks*128
    const int qbB = t16b * 1024 + lane * 4;

    float mrow[4], lrow[4];     // [tt*2 + half]
#pragma unroll
    for (int i = 0; i < 4; i++) { mrow[i] = -1e30f; lrow[i] = 0.f; }
    float Oac[2][8][4];
#pragma unroll
    for (int tt = 0; tt < 2; tt++)
#pragma unroll
        for (int nt = 0; nt < 8; nt++)
#pragma unroll
            for (int u = 0; u < 4; u++) Oac[tt][nt][u] = 0.f;

    const int NCH = SS / 64;   // 32
    for (int t = 0; t < NCH; t++) {
        // ---- wait K(t) (and Q on t=0) ----
        mbar_wait(kbar, t & 1);

        // ---- S = Q @ K^T (keys arrive sigma-permuted; transparent here) ----
        float Sac[2][8][4];
#pragma unroll
        for (int tt = 0; tt < 2; tt++)
#pragma unroll
            for (int nt = 0; nt < 8; nt++)
#pragma unroll
                for (int u = 0; u < 4; u++) Sac[tt][nt][u] = 0.f;

#pragma unroll
        for (int ks = 0; ks < 8; ks++) {
            const uint4 qf0 = *(const uint4*)&Qs[qbA + ks * 128];
            const uint4 qf1 = *(const uint4*)&Qs[qbB + ks * 128];
#pragma unroll
            for (int nt = 0; nt < 8; nt++) {
                const uint2 kf = *(const uint2*)&Ks[(ks * 8 + nt) * 64 + lane * 2];
                mma_tf32(Sac[0][nt], qf0, kf);
                mma_tf32(Sac[1][nt], qf1, kf);
            }
        }

        // all warps done reading Ks -> refill with K(t+1)
        __syncthreads();
        if (tid == 0 && t + 1 < NCH) {
            mbar_expect(kbar, 16384);
            bulk_g2s(smem_u32(Ks), Kg + (long long)(t + 1) * 4096, 16384, kbar);
        }

        // ---- online softmax per A-tile; P stays in Sac ----
#pragma unroll
        for (int tt = 0; tt < 2; tt++) {
            float mx0 = -1e30f, mx1 = -1e30f;
#pragma unroll
            for (int nt = 0; nt < 8; nt++) {
                mx0 = fmaxf(mx0, fmaxf(Sac[tt][nt][0], Sac[tt][nt][1]));
                mx1 = fmaxf(mx1, fmaxf(Sac[tt][nt][2], Sac[tt][nt][3]));
            }
#pragma unroll
            for (int off = 1; off < 4; off <<= 1) {
                mx0 = fmaxf(mx0, __shfl_xor_sync(0xFFFFFFFFu, mx0, off));
                mx1 = fmaxf(mx1, __shfl_xor_sync(0xFFFFFFFFu, mx1, off));
            }
            const float mn0 = fmaxf(mrow[tt*2+0], mx0);
            const float mn1 = fmaxf(mrow[tt*2+1], mx1);
            const float al0 = __expf(mrow[tt*2+0] - mn0);
            const float al1 = __expf(mrow[tt*2+1] - mn1);
            mrow[tt*2+0] = mn0; mrow[tt*2+1] = mn1;

            float rs0 = 0.f, rs1 = 0.f;
#pragma unroll
            for (int nt = 0; nt < 8; nt++) {
                float p0 = __expf(Sac[tt][nt][0] - mn0);
                float p1 = __expf(Sac[tt][nt][1] - mn0);
                float p2 = __expf(Sac[tt][nt][2] - mn1);
                float p3 = __expf(Sac[tt][nt][3] - mn1);
                Sac[tt][nt][0] = p0; Sac[tt][nt][1] = p1;
                Sac[tt][nt][2] = p2; Sac[tt][nt][3] = p3;
                rs0 += p0 + p1;
                rs1 += p2 + p3;
            }
#pragma unroll
            for (int off = 1; off < 4; off <<= 1) {
                rs0 += __shfl_xor_sync(0xFFFFFFFFu, rs0, off);
                rs1 += __shfl_xor_sync(0xFFFFFFFFu, rs1, off);
            }
            lrow[tt*2+0] = lrow[tt*2+0] * al0 + rs0;
            lrow[tt*2+1] = lrow[tt*2+1] * al1 + rs1;
#pragma unroll
            for (int nt = 0; nt < 8; nt++) {
                Oac[tt][nt][0] *= al0; Oac[tt][nt][1] *= al0;
                Oac[tt][nt][2] *= al1; Oac[tt][nt][3] *= al1;
            }
        }

        // ---- wait V(t), then O += P @ V with P from registers ----
        // A-frag for key-group ks of tile tt = {c0, c2, c1, c3} of Sac[tt][ks]
        mbar_wait(vbar, t & 1);
#pragma unroll
        for (int ks = 0; ks < 8; ks++) {
            uint4 pf0, pf1;
            pf0.x = __float_as_uint(Sac[0][ks][0]);
            pf0.y = __float_as_uint(Sac[0][ks][2]);
            pf0.z = __float_as_uint(Sac[0][ks][1]);
            pf0.w = __float_as_uint(Sac[0][ks][3]);
            pf1.x = __float_as_uint(Sac[1][ks][0]);
            pf1.y = __float_as_uint(Sac[1][ks][2]);
            pf1.z = __float_as_uint(Sac[1][ks][1]);
            pf1.w = __float_as_uint(Sac[1][ks][3]);
#pragma unroll
            for (int nt = 0; nt < 8; nt++) {
                const uint2 vf = *(const uint2*)&Vs[(ks * 8 + nt) * 64 + lane * 2];
                mma_tf32(Oac[0][nt], pf0, vf);
                mma_tf32(Oac[1][nt], pf1, vf);
            }
        }

        // all warps done reading Vs -> refill with V(t+1)
        __syncthreads();
        if (tid == 0 && t + 1 < NCH) {
            mbar_expect(vbar, 16384);
            bulk_g2s(smem_u32(Vs), Vg + (long long)(t + 1) * 4096, 16384, vbar);
        }
    }

    __syncthreads();
    if (tid == 0) { mbar_inval(kbar); mbar_inval(vbar); }

    // ---- epilogue: normalize, rna-round, write A-frag-major into xr ----
    // ctx row m = b*SS + q0 + wq*32 + tt*16 + {g, g+8}; col = h*64 + nt*8 + {2a, 2a+1}
    const int b = bh / HH, h = bh % HH;
    const long long mbase = (long long)((b * SS + q0) >> 7) * 32 * 4096;
    const int off = ((g << 2) | ((2 * a) & 3)) * 4 + (((2 * a) & 4) ? 2 : 0);
#pragma unroll
    for (int tt = 0; tt < 2; tt++) {
        const int t16 = wq * 2 + tt;
        const float rl0 = 1.0f / lrow[tt*2+0], rl1 = 1.0f / lrow[tt*2+1];
#pragma unroll
        for (int nt = 0; nt < 8; nt++) {
            long long adr = mbase + (long long)(h * 2 + (nt >> 2)) * 4096
                          + (t16 * 4 + (nt & 3)) * 128 + off;
            // (v0,v2) rows g,g+8 at col 2a; (v1,v3) at col 2a+1 (+4)
            *(float2*)&xr[adr] =
                make_float2(rna_tf32(Oac[tt][nt][0] * rl0), rna_tf32(Oac[tt][nt][2] * rl1));
            *(float2*)&xr[adr + 4] =
                make_float2(rna_tf32(Oac[tt][nt][1] * rl0), rna_tf32(Oac[tt][nt][3] * rl1));
        }
    }
}

// ---------------------------------------------------------------------------
extern "C" void kernel_launch(void* const* d_in, const int* in_sizes, int n_in,
                              void* d_out, int out_size)
{
    const float* x   = (const float*)d_in[0];
    const float* q_w = (const float*)d_in[1];
    const float* q_b = (const float*)d_in[2];
    const float* k_w = (const float*)d_in[3];
    const float* k_b = (const float*)d_in[4];
    const float* v_w = (const float*)d_in[5];
    const float* v_b = (const float*)d_in[6];
    const float* o_w = (const float*)d_in[7];
    const float* o_b = (const float*)d_in[8];
    float* out = (float*)d_out;

    float *qbuf, *kbuf, *vbuf, *xr, *wq, *wk, *wv, *wo;
    cudaGetSymbolAddress((void**)&qbuf, g_q);
    cudaGetSymbolAddress((void**)&kbuf, g_k);
    cudaGetSymbolAddress((void**)&vbuf, g_v);
    cudaGetSymbolAddress((void**)&xr, g_xr);
    cudaGetSymbolAddress((void**)&wq, g_wq);
    cudaGetSymbolAddress((void**)&wk, g_wk);
    cudaGetSymbolAddress((void**)&wv, g_wv);
    cudaGetSymbolAddress((void**)&wo, g_wo);

    cudaFuncSetAttribute(attn7_kernel, cudaFuncAttributeMaxDynamicSharedMemorySize,
                         ATTN_SMEM);
    cudaFuncSetAttribute(mma_gemm2<0>, cudaFuncAttributeMaxDynamicSharedMemorySize,
                         GSM_BYTES);
    cudaFuncSetAttribute(mma_gemm2<1>, cudaFuncAttributeMaxDynamicSharedMemorySize,
                         GSM_BYTES);

    // layout permutation + tf32 rounding
    dim3 pga(32, MTOK / 128);          // (32, 32)
    permA_kernel<<<pga, 128>>>(x, xr);
    dim3 pgb(32, EE / 128, 4);         // (32, 8, 4)
    permB_kernel<<<pgb, 128>>>(q_w, k_w, v_w, o_w, wq, wk, wv, wo);

    // fused QKV projections (K epilogue applies sigma key permutation)
    dim3 qgrid(EE / 128, MTOK / 128, 3);
    mma_gemm2<0><<<qgrid, 256, GSM_BYTES>>>(xr, wq, wk, wv, q_b, k_b, v_b,
                                            qbuf, kbuf, vbuf);

    // flash attention (writes A-frag-major O directly into xr)
    dim3 agrid(SS / AQ, BHH);          // (16, 32)
    attn7_kernel<<<agrid, 128, ATTN_SMEM>>>(qbuf, kbuf, vbuf, xr);

    // output projection (consumes xr directly; no permA(ctx) pass)
    dim3 ogrid(EE / 128, MTOK / 128, 1);
    mma_gemm2<1><<<ogrid, 256, GSM_BYTES>>>(xr, wo, nullptr, nullptr,
                                            o_b, nullptr, nullptr,
                                            out, nullptr, nullptr);
}